// round 15
// baseline (speedup 1.0000x reference)
#include <cuda_runtime.h>
#include <math.h>

#define UC 100000
#define IC 50000
#define NC 150000
#define DD 64
#define EC 3000000
#define BB 8192
#define NEG_SLOPE 0.2f
#define NB 586               // scan blocks: 586*256 >= NC
#define ECHUNK 128           // edges per spmm warp
#define NCH ((EC + ECHUNK - 1) / ECHUNK)

typedef unsigned long long u64;
typedef unsigned int u32;

// ---------------- packed f32x2 / bf16 helpers ------------------------------------
__device__ __forceinline__ u64 pk2(float x, float y) {
    u64 r; asm("mov.b64 %0,{%1,%2};" : "=l"(r) : "f"(x), "f"(y)); return r;
}
__device__ __forceinline__ void upk2(u64 v, float& x, float& y) {
    asm("mov.b64 {%0,%1},%2;" : "=f"(x), "=f"(y) : "l"(v));
}
__device__ __forceinline__ u64 fma2(u64 a, u64 b, u64 c) {
    u64 d; asm("fma.rn.f32x2 %0,%1,%2,%3;" : "=l"(d) : "l"(a), "l"(b), "l"(c)); return d;
}
__device__ __forceinline__ u32 bf2(float lo, float hi) {
    u32 r; asm("cvt.rn.bf16x2.f32 %0,%1,%2;" : "=r"(r) : "f"(hi), "f"(lo)); return r;
}
__device__ __forceinline__ u64 unbf(u32 v) {
    return pk2(__uint_as_float(v << 16), __uint_as_float(v & 0xffff0000u));
}

// ---------------- device scratch ------------------------------------------------
__device__ u32    g_e0h[NC * DD / 2];   // bf16 concat(uemb,iemb), row = 128B
__device__ u32    g_egoh[NC * DD / 2];  // bf16 layer-0 ego, row = 128B
__device__ float  g_side[NC * DD];      // SpMM output (fp32, zeroed)
__device__ float  g_n1[NC * DD];
__device__ float  g_n2[NC * DD];
__device__ int    g_rowptr[NC + 1];
__device__ int    g_cnt[NC];            // (a) counts, (b) bump-allocator bases
__device__ int    g_bsum[640];
__device__ int    g_boff[640];
__device__ float2 g_epk[EC];            // packed (byte_offset_as_float, val)
__device__ double g_acc[2];

// ---------------- histogram + bf16 embedding concat (merged) ----------------------
__global__ void k_inithist(const int* __restrict__ rows, const float* __restrict__ uemb,
                           const float* __restrict__ iemb) {
    int stride = gridDim.x * blockDim.x;
    int t0 = blockIdx.x * blockDim.x + threadIdx.x;
    const int4* r4 = (const int4*)rows;
    for (int e = t0; e < EC / 4; e += stride) {
        int4 v = r4[e];
        atomicAdd(&g_cnt[v.x], 1);
        atomicAdd(&g_cnt[v.y], 1);
        atomicAdd(&g_cnt[v.z], 1);
        atomicAdd(&g_cnt[v.w], 1);
    }
    const int UQ = UC * DD / 4;
    const int NQ = NC * DD / 4;
    u64* dst = (u64*)g_e0h;
    const float4* su = (const float4*)uemb;
    const float4* si = (const float4*)iemb;
    for (int i = t0; i < NQ; i += stride) {
        float4 v = (i < UQ) ? su[i] : si[i - UQ];
        u32 a = bf2(v.x, v.y), b = bf2(v.z, v.w);
        dst[i] = ((u64)b << 32) | a;
    }
}

// ---------------- parallel 3-phase scan (all coalesced) ---------------------------
__global__ void k_scan1() {
    __shared__ int s[256];
    int b = blockIdx.x, t = threadIdx.x;
    int i = b * 256 + t;
    int v = (i < NC) ? g_cnt[i] : 0;
    s[t] = v;
    __syncthreads();
#pragma unroll
    for (int o = 128; o > 0; o >>= 1) {
        if (t < o) s[t] += s[t + o];
        __syncthreads();
    }
    if (t == 0) g_bsum[b] = s[0];
}

__global__ void k_scan2() {
    __shared__ int s[1024];
    int t = threadIdx.x;
    int v = (t < NB) ? g_bsum[t] : 0;
    s[t] = v;
    __syncthreads();
#pragma unroll
    for (int o = 1; o < 1024; o <<= 1) {
        int x = (t >= o) ? s[t - o] : 0;
        __syncthreads();
        s[t] += x;
        __syncthreads();
    }
    if (t < NB) g_boff[t] = s[t] - v;
    if (t == 1023) g_rowptr[NC] = s[1023];
}

__global__ void k_scan3() {
    __shared__ int s[256];
    int b = blockIdx.x, t = threadIdx.x;
    int i = b * 256 + t;
    int v = (i < NC) ? g_cnt[i] : 0;
    s[t] = v;
    __syncthreads();
#pragma unroll
    for (int o = 1; o < 256; o <<= 1) {
        int x = (t >= o) ? s[t - o] : 0;
        __syncthreads();
        s[t] += x;
        __syncthreads();
    }
    int p = g_boff[b] + s[t] - v;
    if (i < NC) {
        g_rowptr[i] = p;
        g_cnt[i] = p;
    }
}

// scatter: store byte offset into 128B-row bf16 table (col*128) + val
__global__ void k_scatter(const int* __restrict__ rows, const int* __restrict__ cols,
                          const float* __restrict__ vals) {
    int stride = gridDim.x * blockDim.x;
    for (int e = blockIdx.x * blockDim.x + threadIdx.x; e < EC; e += stride) {
        int r = rows[e];
        int p = atomicAdd(&g_cnt[r], 1);
        g_epk[p] = make_float2(__int_as_float(cols[e] << 7), vals[e]);
    }
}

// ---------------- SpMM: edge-balanced 128-edge chunks per warp --------------------
// Rows fully inside a chunk: direct store. Boundary rows: atomicAdd into zeroed g_side.
__global__ __launch_bounds__(256) void k_spmm(const u32* __restrict__ base) {
    int chunk = (blockIdx.x * blockDim.x + threadIdx.x) >> 5;
    int lane = threadIdx.x & 31;
    int e0 = chunk * ECHUNK;
    if (e0 >= EC) return;
    int e1 = min(e0 + ECHUNK, EC);
    const char* bp = (const char*)base + lane * 4;

    // binary search: largest r in [0, NC) with rowptr[r] <= e0
    int a = 0, b = NC;
    while (a + 1 < b) {
        int m = (a + b) >> 1;
        if (__ldg(&g_rowptr[m]) <= e0) a = m; else b = m;
    }
    int r = a;
    bool firstAtomic = (__ldg(&g_rowptr[r]) < e0);   // row started in a prior chunk
    int rend = __ldg(&g_rowptr[r + 1]);

    u64 a0 = 0ull, a1 = 0ull;
    int i = e0;
    while (true) {
        int stop = min(rend, e1);
        for (; i + 1 < stop; i += 2) {
            float2 p0 = g_epk[i], p1 = g_epk[i + 1];     // broadcast L1 loads
            u32 v0 = *(const u32*)(bp + __float_as_int(p0.x));
            u32 v1 = *(const u32*)(bp + __float_as_int(p1.x));
            a0 = fma2(pk2(p0.y, p0.y), unbf(v0), a0);
            a1 = fma2(pk2(p1.y, p1.y), unbf(v1), a1);
        }
        if (i < stop) {
            float2 p = g_epk[i];
            u32 v = *(const u32*)(bp + __float_as_int(p.x));
            a0 = fma2(pk2(p.y, p.y), unbf(v), a0);
            i++;
        }
        bool rowDone = (stop == rend);
        float x0, y0, x1, y1;
        upk2(a0, x0, y0);
        upk2(a1, x1, y1);
        float sx = x0 + x1, sy = y0 + y1;
        float* dst = &g_side[(size_t)r * DD + lane * 2];
        if (rowDone && !firstAtomic) {
            *(float2*)dst = make_float2(sx, sy);
        } else {
            atomicAdd(dst, sx);
            atomicAdd(dst + 1, sy);
        }
        if (stop == e1) break;
        a0 = 0ull; a1 = 0ull;
        firstAtomic = false;
        r++;
        rend = __ldg(&g_rowptr[r + 1]);
        while (rend <= i) { r++; rend = __ldg(&g_rowptr[r + 1]); }  // skip empty rows
    }
}

// ---------------- fused dual GEMM (R2-proven core) --------------------------------
#define PADX 132
__global__ __launch_bounds__(256) void k_gemm(const float* __restrict__ Wg,
                                              const float* __restrict__ bg,
                                              const float* __restrict__ Wm,
                                              const float* __restrict__ bm,
                                              int layer) {
    __shared__ float sX[DD][PADX];   // [k][row]
    __shared__ float sW[DD][DD];     // [k][c]
    int tid = threadIdx.x;
    int rowBase = blockIdx.x * 128;

    for (int i = tid; i < DD * DD / 4; i += 256)
        ((float4*)sW)[i] = ((const float4*)Wg)[i];
    for (int i = tid; i < 128 * 16; i += 256) {
        int r = i >> 4, k4 = (i & 15) * 4;
        int gr = rowBase + r;
        float4 v = (gr < NC) ? *(const float4*)&g_side[(size_t)gr * DD + k4]
                             : make_float4(0.f, 0.f, 0.f, 0.f);
        sX[k4][r] = v.x; sX[k4 + 1][r] = v.y; sX[k4 + 2][r] = v.z; sX[k4 + 3][r] = v.w;
    }
    __syncthreads();

    // layer 0: re-zero this tile of g_side so the next (atomic) spmm starts clean
    if (layer == 0) {
        for (int i = tid; i < 128 * 16; i += 256) {
            int r = i >> 4, k4 = (i & 15) * 4;
            int gr = rowBase + r;
            if (gr < NC)
                *(float4*)&g_side[(size_t)gr * DD + k4] = make_float4(0.f, 0.f, 0.f, 0.f);
        }
    }

    int ct = tid & 15, rt = tid >> 4;
    int c0 = ct * 4, r0 = rt * 8;

    u64 acc[4][4];
#pragma unroll
    for (int p = 0; p < 4; p++)
#pragma unroll
        for (int j = 0; j < 4; j++) acc[p][j] = 0ull;

#pragma unroll 8
    for (int k = 0; k < DD; k++) {
        ulonglong2 A0 = *(const ulonglong2*)&sX[k][r0];
        ulonglong2 A1 = *(const ulonglong2*)&sX[k][r0 + 4];
        float4 bv = *(const float4*)&sW[k][c0];
        u64 B0 = pk2(bv.x, bv.x), B1 = pk2(bv.y, bv.y);
        u64 B2 = pk2(bv.z, bv.z), B3 = pk2(bv.w, bv.w);
        acc[0][0] = fma2(A0.x, B0, acc[0][0]); acc[0][1] = fma2(A0.x, B1, acc[0][1]);
        acc[0][2] = fma2(A0.x, B2, acc[0][2]); acc[0][3] = fma2(A0.x, B3, acc[0][3]);
        acc[1][0] = fma2(A0.y, B0, acc[1][0]); acc[1][1] = fma2(A0.y, B1, acc[1][1]);
        acc[1][2] = fma2(A0.y, B2, acc[1][2]); acc[1][3] = fma2(A0.y, B3, acc[1][3]);
        acc[2][0] = fma2(A1.x, B0, acc[2][0]); acc[2][1] = fma2(A1.x, B1, acc[2][1]);
        acc[2][2] = fma2(A1.x, B2, acc[2][2]); acc[2][3] = fma2(A1.x, B3, acc[2][3]);
        acc[3][0] = fma2(A1.y, B0, acc[3][0]); acc[3][1] = fma2(A1.y, B1, acc[3][1]);
        acc[3][2] = fma2(A1.y, B2, acc[3][2]); acc[3][3] = fma2(A1.y, B3, acc[3][3]);
    }

    float t[8][4];
#pragma unroll
    for (int p = 0; p < 4; p++)
#pragma unroll
        for (int j = 0; j < 4; j++) {
            float lo, hi;
            upk2(acc[p][j], lo, hi);
            float bv = __ldg(&bg[c0 + j]);
            lo += bv; hi += bv;
            t[2 * p][j]     = (lo > 0.f) ? lo : NEG_SLOPE * lo;
            t[2 * p + 1][j] = (hi > 0.f) ? hi : NEG_SLOPE * hi;
        }
    __syncthreads();

    for (int i = tid; i < DD * DD / 4; i += 256)
        ((float4*)sW)[i] = ((const float4*)Wm)[i];
#pragma unroll
    for (int i = 0; i < 8; i++)
#pragma unroll
        for (int j = 0; j < 4; j++) sX[c0 + j][r0 + i] = t[i][j];
    __syncthreads();

#pragma unroll
    for (int p = 0; p < 4; p++)
#pragma unroll
        for (int j = 0; j < 4; j++) acc[p][j] = 0ull;

#pragma unroll 8
    for (int k = 0; k < DD; k++) {
        ulonglong2 A0 = *(const ulonglong2*)&sX[k][r0];
        ulonglong2 A1 = *(const ulonglong2*)&sX[k][r0 + 4];
        float4 bv = *(const float4*)&sW[k][c0];
        u64 B0 = pk2(bv.x, bv.x), B1 = pk2(bv.y, bv.y);
        u64 B2 = pk2(bv.z, bv.z), B3 = pk2(bv.w, bv.w);
        acc[0][0] = fma2(A0.x, B0, acc[0][0]); acc[0][1] = fma2(A0.x, B1, acc[0][1]);
        acc[0][2] = fma2(A0.x, B2, acc[0][2]); acc[0][3] = fma2(A0.x, B3, acc[0][3]);
        acc[1][0] = fma2(A0.y, B0, acc[1][0]); acc[1][1] = fma2(A0.y, B1, acc[1][1]);
        acc[1][2] = fma2(A0.y, B2, acc[1][2]); acc[1][3] = fma2(A0.y, B3, acc[1][3]);
        acc[2][0] = fma2(A1.x, B0, acc[2][0]); acc[2][1] = fma2(A1.x, B1, acc[2][1]);
        acc[2][2] = fma2(A1.x, B2, acc[2][2]); acc[2][3] = fma2(A1.x, B3, acc[2][3]);
        acc[3][0] = fma2(A1.y, B0, acc[3][0]); acc[3][1] = fma2(A1.y, B1, acc[3][1]);
        acc[3][2] = fma2(A1.y, B2, acc[3][2]); acc[3][3] = fma2(A1.y, B3, acc[3][3]);
    }

    float y[8][4];
#pragma unroll
    for (int p = 0; p < 4; p++)
#pragma unroll
        for (int j = 0; j < 4; j++) {
            float lo, hi;
            upk2(acc[p][j], lo, hi);
            float bv = __ldg(&bm[c0 + j]);
            y[2 * p][j] = lo + bv;
            y[2 * p + 1][j] = hi + bv;
        }

    float* nbuf = (layer == 0) ? g_n1 : g_n2;
#pragma unroll
    for (int i = 0; i < 8; i++) {
        float ss = y[i][0] * y[i][0] + y[i][1] * y[i][1] + y[i][2] * y[i][2] + y[i][3] * y[i][3];
#pragma unroll
        for (int o = 8; o > 0; o >>= 1) ss += __shfl_xor_sync(0xffffffffu, ss, o, 16);
        float inv = 1.f / fmaxf(sqrtf(ss), 1e-12f);
        int gr = rowBase + r0 + i;
        if (gr < NC) {
            if (layer == 0) {
                u32 lo = bf2(y[i][0], y[i][1]), hi = bf2(y[i][2], y[i][3]);
                *(u64*)&g_egoh[(size_t)gr * 32 + c0 / 2] = ((u64)hi << 32) | lo;
            }
            *(float4*)&nbuf[(size_t)gr * DD + c0] =
                make_float4(y[i][0] * inv, y[i][1] * inv, y[i][2] * inv, y[i][3] * inv);
        }
    }
}

// ---------------- BPR scoring + regularization ------------------------------------
__global__ void k_score(const int* __restrict__ user, const int* __restrict__ pos,
                        const int* __restrict__ neg, const float* __restrict__ uemb,
                        const float* __restrict__ iemb) {
    __shared__ float sb[8];
    __shared__ float sr[8];
    int tid = threadIdx.x;
    int wid = tid >> 5, lane = tid & 31;
    int b = blockIdx.x * 8 + wid;
    float sp = 0.f, rg = 0.f;
    if (b < BB) {
        int uu = user[b], pp = pos[b], nn = neg[b];
        size_t off = (size_t)lane * 2;
        const float* u0 = uemb + (size_t)uu * DD + off;
        const float* p0 = iemb + (size_t)pp * DD + off;
        const float* n0 = iemb + (size_t)nn * DD + off;
        const float* u1 = g_n1 + (size_t)uu * DD + off;
        const float* p1 = g_n1 + (size_t)(UC + pp) * DD + off;
        const float* n1 = g_n1 + (size_t)(UC + nn) * DD + off;
        const float* u2 = g_n2 + (size_t)uu * DD + off;
        const float* p2 = g_n2 + (size_t)(UC + pp) * DD + off;
        const float* n2 = g_n2 + (size_t)(UC + nn) * DD + off;
        float ps = 0.f, ns = 0.f;
        float2 ue = *(const float2*)u0, pe = *(const float2*)p0, ne = *(const float2*)n0;
        rg += ue.x * ue.x + ue.y * ue.y + pe.x * pe.x + pe.y * pe.y + ne.x * ne.x + ne.y * ne.y;
        ps += ue.x * pe.x + ue.y * pe.y;
        ns += ue.x * ne.x + ue.y * ne.y;
        float2 a1 = *(const float2*)u1, b1 = *(const float2*)p1, c1 = *(const float2*)n1;
        ps += a1.x * b1.x + a1.y * b1.y;
        ns += a1.x * c1.x + a1.y * c1.y;
        float2 a2 = *(const float2*)u2, b2 = *(const float2*)p2, c2 = *(const float2*)n2;
        ps += a2.x * b2.x + a2.y * b2.y;
        ns += a2.x * c2.x + a2.y * c2.y;
#pragma unroll
        for (int o = 16; o > 0; o >>= 1) {
            ps += __shfl_xor_sync(0xffffffffu, ps, o);
            ns += __shfl_xor_sync(0xffffffffu, ns, o);
            rg += __shfl_xor_sync(0xffffffffu, rg, o);
        }
        float x = ns - ps;
        sp = fmaxf(x, 0.f) + log1pf(expf(-fabsf(x)));
    }
    if (lane == 0) { sb[wid] = sp; sr[wid] = rg; }
    __syncthreads();
    if (tid == 0) {
        float s1 = 0.f, s2 = 0.f;
        for (int i = 0; i < 8; i++) { s1 += sb[i]; s2 += sr[i]; }
        atomicAdd(&g_acc[0], (double)s1);
        atomicAdd(&g_acc[1], (double)s2);
    }
}

__global__ void k_final(float* out) {
    out[0] = (float)(g_acc[0] / (double)BB);
    out[1] = (float)(0.0001 * 0.5 * g_acc[1] / (double)BB);
}

// ---------------- launch -----------------------------------------------------------
extern "C" void kernel_launch(void* const* d_in, const int* in_sizes, int n_in,
                              void* d_out, int out_size) {
    (void)in_sizes; (void)n_in; (void)out_size;
    const int*   user = (const int*)d_in[0];
    const int*   pos  = (const int*)d_in[1];
    const int*   neg  = (const int*)d_in[2];
    const int*   rows = (const int*)d_in[3];
    const int*   cols = (const int*)d_in[4];
    const float* vals = (const float*)d_in[5];
    const float* uemb = (const float*)d_in[6];
    const float* iemb = (const float*)d_in[7];
    const float* Wg0  = (const float*)d_in[8];
    const float* bg0  = (const float*)d_in[9];
    const float* Wm0  = (const float*)d_in[10];
    const float* bm0  = (const float*)d_in[11];
    const float* Wg1  = (const float*)d_in[12];
    const float* bg1  = (const float*)d_in[13];
    const float* Wm1  = (const float*)d_in[14];
    const float* bm1  = (const float*)d_in[15];
    float* out = (float*)d_out;

    u32* e0h  = nullptr;
    u32* egoh = nullptr;
    void* cntp = nullptr;
    void* accp = nullptr;
    void* sidep = nullptr;
    cudaGetSymbolAddress((void**)&e0h, g_e0h);
    cudaGetSymbolAddress((void**)&egoh, g_egoh);
    cudaGetSymbolAddress(&cntp, g_cnt);
    cudaGetSymbolAddress(&accp, g_acc);
    cudaGetSymbolAddress(&sidep, g_side);

    cudaMemsetAsync(cntp, 0, NC * sizeof(int));
    cudaMemsetAsync(accp, 0, 2 * sizeof(double));
    cudaMemsetAsync(sidep, 0, (size_t)NC * DD * sizeof(float));  // spmm0 atomic base

    k_inithist<<<2048, 256>>>(rows, uemb, iemb);
    k_scan1<<<NB, 256>>>();
    k_scan2<<<1, 1024>>>();
    k_scan3<<<NB, 256>>>();
    k_scatter<<<2048, 256>>>(rows, cols, vals);

    int spmm_blocks = (NCH * 32 + 255) / 256;
    int gemm_blocks = (NC + 127) / 128;

    k_spmm<<<spmm_blocks, 256>>>(e0h);
    k_gemm<<<gemm_blocks, 256>>>(Wg0, bg0, Wm0, bm0, 0);   // also re-zeroes g_side
    k_spmm<<<spmm_blocks, 256>>>(egoh);
    k_gemm<<<gemm_blocks, 256>>>(Wg1, bg1, Wm1, bm1, 1);

    k_score<<<(BB + 7) / 8, 256>>>(user, pos, neg, uemb, iemb);
    k_final<<<1, 1>>>(out);
}

// round 16
// speedup vs baseline: 1.2012x; 1.2012x over previous
#include <cuda_runtime.h>
#include <math.h>

#define UC 100000
#define IC 50000
#define NC 150000
#define DD 64
#define EC 3000000
#define BB 8192
#define NEG_SLOPE 0.2f
#define NB 586               // scan blocks: 586*256 >= NC

typedef unsigned long long u64;
typedef unsigned int u32;

// ---------------- packed f32x2 / bf16 helpers ------------------------------------
__device__ __forceinline__ u64 pk2(float x, float y) {
    u64 r; asm("mov.b64 %0,{%1,%2};" : "=l"(r) : "f"(x), "f"(y)); return r;
}
__device__ __forceinline__ void upk2(u64 v, float& x, float& y) {
    asm("mov.b64 {%0,%1},%2;" : "=f"(x), "=f"(y) : "l"(v));
}
__device__ __forceinline__ u64 fma2(u64 a, u64 b, u64 c) {
    u64 d; asm("fma.rn.f32x2 %0,%1,%2,%3;" : "=l"(d) : "l"(a), "l"(b), "l"(c)); return d;
}
__device__ __forceinline__ u32 bf2(float lo, float hi) {
    u32 r; asm("cvt.rn.bf16x2.f32 %0,%1,%2;" : "=r"(r) : "f"(hi), "f"(lo)); return r;
}
__device__ __forceinline__ float bflo(u32 v) { return __uint_as_float(v << 16); }
__device__ __forceinline__ float bfhi(u32 v) { return __uint_as_float(v & 0xffff0000u); }

// ---------------- device scratch ------------------------------------------------
__device__ u32    g_e0h[NC * DD / 2];    // bf16 concat(uemb,iemb), row = 128B
__device__ u32    g_egoh[NC * DD / 2];   // bf16 layer-0 ego, row = 128B
__device__ u32    g_sideh[NC * DD / 2];  // bf16 SpMM output, row = 128B
__device__ float  g_n1[NC * DD];
__device__ float  g_n2[NC * DD];
__device__ int    g_rowptr[NC + 1];
__device__ int    g_cnt[NC];             // (a) counts, (b) bump-allocator bases
__device__ int    g_bsum[640];
__device__ int    g_boff[640];
__device__ float2 g_epk[EC];             // packed (byte_offset_as_float, val)
__device__ double g_acc[2];

// ---------------- histogram + bf16 embedding concat (merged) ----------------------
__global__ void k_inithist(const int* __restrict__ rows, const float* __restrict__ uemb,
                           const float* __restrict__ iemb) {
    int stride = gridDim.x * blockDim.x;
    int t0 = blockIdx.x * blockDim.x + threadIdx.x;
    const int4* r4 = (const int4*)rows;
    for (int e = t0; e < EC / 4; e += stride) {
        int4 v = r4[e];
        atomicAdd(&g_cnt[v.x], 1);
        atomicAdd(&g_cnt[v.y], 1);
        atomicAdd(&g_cnt[v.z], 1);
        atomicAdd(&g_cnt[v.w], 1);
    }
    const int UQ = UC * DD / 4;
    const int NQ = NC * DD / 4;
    u64* dst = (u64*)g_e0h;
    const float4* su = (const float4*)uemb;
    const float4* si = (const float4*)iemb;
    for (int i = t0; i < NQ; i += stride) {
        float4 v = (i < UQ) ? su[i] : si[i - UQ];
        u32 a = bf2(v.x, v.y), b = bf2(v.z, v.w);
        dst[i] = ((u64)b << 32) | a;
    }
}

// ---------------- parallel 3-phase scan (all coalesced) ---------------------------
__global__ void k_scan1() {
    __shared__ int s[256];
    int b = blockIdx.x, t = threadIdx.x;
    int i = b * 256 + t;
    int v = (i < NC) ? g_cnt[i] : 0;
    s[t] = v;
    __syncthreads();
#pragma unroll
    for (int o = 128; o > 0; o >>= 1) {
        if (t < o) s[t] += s[t + o];
        __syncthreads();
    }
    if (t == 0) g_bsum[b] = s[0];
}

__global__ void k_scan2() {
    __shared__ int s[1024];
    int t = threadIdx.x;
    int v = (t < NB) ? g_bsum[t] : 0;
    s[t] = v;
    __syncthreads();
#pragma unroll
    for (int o = 1; o < 1024; o <<= 1) {
        int x = (t >= o) ? s[t - o] : 0;
        __syncthreads();
        s[t] += x;
        __syncthreads();
    }
    if (t < NB) g_boff[t] = s[t] - v;
    if (t == 1023) g_rowptr[NC] = s[1023];
}

__global__ void k_scan3() {
    __shared__ int s[256];
    int b = blockIdx.x, t = threadIdx.x;
    int i = b * 256 + t;
    int v = (i < NC) ? g_cnt[i] : 0;
    s[t] = v;
    __syncthreads();
#pragma unroll
    for (int o = 1; o < 256; o <<= 1) {
        int x = (t >= o) ? s[t - o] : 0;
        __syncthreads();
        s[t] += x;
        __syncthreads();
    }
    int p = g_boff[b] + s[t] - v;
    if (i < NC) {
        g_rowptr[i] = p;
        g_cnt[i] = p;
    }
}

// scatter: store byte offset into 128B-row bf16 table (col*128) + val
__global__ void k_scatter(const int* __restrict__ rows, const int* __restrict__ cols,
                          const float* __restrict__ vals) {
    int stride = gridDim.x * blockDim.x;
    for (int e = blockIdx.x * blockDim.x + threadIdx.x; e < EC; e += stride) {
        int r = rows[e];
        int p = atomicAdd(&g_cnt[r], 1);
        g_epk[p] = make_float2(__int_as_float(cols[e] << 7), vals[e]);
    }
}

// ---------------- SpMM: warp per row, bf16 gather + bf16 output (R14-proven) ------
__global__ __launch_bounds__(256) void k_spmm(const u32* __restrict__ base) {
    int w = (blockIdx.x * blockDim.x + threadIdx.x) >> 5;
    int lane = threadIdx.x & 31;
    if (w >= NC) return;
    const char* bp = (const char*)base + lane * 4;   // 2 bf16 dims per lane
    int s = g_rowptr[w], e = g_rowptr[w + 1];
    u64 a0 = 0ull, a1 = 0ull;
    int i = s;
    if (i < e && (i & 1)) {   // head-peel to even index for aligned float4 loads
        float2 p = g_epk[i];
        u32 v = *(const u32*)(bp + __float_as_int(p.x));
        a0 = fma2(pk2(p.y, p.y), pk2(bflo(v), bfhi(v)), a0);
        i++;
    }
    for (; i + 1 < e; i += 2) {
        float4 pq = *(const float4*)&g_epk[i];       // 2 edges, one LDG.128
        u32 v0 = *(const u32*)(bp + __float_as_int(pq.x));
        u32 v1 = *(const u32*)(bp + __float_as_int(pq.z));
        a0 = fma2(pk2(pq.y, pq.y), pk2(bflo(v0), bfhi(v0)), a0);
        a1 = fma2(pk2(pq.w, pq.w), pk2(bflo(v1), bfhi(v1)), a1);
    }
    if (i < e) {
        float2 p = g_epk[i];
        u32 v = *(const u32*)(bp + __float_as_int(p.x));
        a0 = fma2(pk2(p.y, p.y), pk2(bflo(v), bfhi(v)), a0);
    }
    float s0x, s0y, s1x, s1y;
    upk2(a0, s0x, s0y);
    upk2(a1, s1x, s1y);
    g_sideh[(size_t)w * 32 + lane] = bf2(s0x + s1x, s0y + s1y);   // bf16 store
}

// ---------------- fused dual GEMM (R2-proven core; bf16 sX load) ------------------
#define PADX 132
__global__ __launch_bounds__(256) void k_gemm(const float* __restrict__ Wg,
                                              const float* __restrict__ bg,
                                              const float* __restrict__ Wm,
                                              const float* __restrict__ bm,
                                              int layer) {
    __shared__ float sX[DD][PADX];   // [k][row]
    __shared__ float sW[DD][DD];     // [k][c]
    int tid = threadIdx.x;
    int rowBase = blockIdx.x * 128;

    for (int i = tid; i < DD * DD / 4; i += 256)
        ((float4*)sW)[i] = ((const float4*)Wg)[i];
    for (int i = tid; i < 128 * 16; i += 256) {
        int r = i >> 4, k4 = (i & 15) * 4;
        int gr = rowBase + r;
        float x0 = 0.f, x1 = 0.f, x2 = 0.f, x3 = 0.f;
        if (gr < NC) {
            u64 pr = *(const u64*)&g_sideh[(size_t)gr * 32 + (i & 15) * 2];
            u32 a = (u32)pr, b = (u32)(pr >> 32);
            x0 = bflo(a); x1 = bfhi(a); x2 = bflo(b); x3 = bfhi(b);
        }
        sX[k4][r] = x0; sX[k4 + 1][r] = x1; sX[k4 + 2][r] = x2; sX[k4 + 3][r] = x3;
    }
    __syncthreads();

    int ct = tid & 15, rt = tid >> 4;
    int c0 = ct * 4, r0 = rt * 8;

    u64 acc[4][4];
#pragma unroll
    for (int p = 0; p < 4; p++)
#pragma unroll
        for (int j = 0; j < 4; j++) acc[p][j] = 0ull;

#pragma unroll 8
    for (int k = 0; k < DD; k++) {
        ulonglong2 A0 = *(const ulonglong2*)&sX[k][r0];
        ulonglong2 A1 = *(const ulonglong2*)&sX[k][r0 + 4];
        float4 bv = *(const float4*)&sW[k][c0];
        u64 B0 = pk2(bv.x, bv.x), B1 = pk2(bv.y, bv.y);
        u64 B2 = pk2(bv.z, bv.z), B3 = pk2(bv.w, bv.w);
        acc[0][0] = fma2(A0.x, B0, acc[0][0]); acc[0][1] = fma2(A0.x, B1, acc[0][1]);
        acc[0][2] = fma2(A0.x, B2, acc[0][2]); acc[0][3] = fma2(A0.x, B3, acc[0][3]);
        acc[1][0] = fma2(A0.y, B0, acc[1][0]); acc[1][1] = fma2(A0.y, B1, acc[1][1]);
        acc[1][2] = fma2(A0.y, B2, acc[1][2]); acc[1][3] = fma2(A0.y, B3, acc[1][3]);
        acc[2][0] = fma2(A1.x, B0, acc[2][0]); acc[2][1] = fma2(A1.x, B1, acc[2][1]);
        acc[2][2] = fma2(A1.x, B2, acc[2][2]); acc[2][3] = fma2(A1.x, B3, acc[2][3]);
        acc[3][0] = fma2(A1.y, B0, acc[3][0]); acc[3][1] = fma2(A1.y, B1, acc[3][1]);
        acc[3][2] = fma2(A1.y, B2, acc[3][2]); acc[3][3] = fma2(A1.y, B3, acc[3][3]);
    }

    float t[8][4];
#pragma unroll
    for (int p = 0; p < 4; p++)
#pragma unroll
        for (int j = 0; j < 4; j++) {
            float lo, hi;
            upk2(acc[p][j], lo, hi);
            float bv = __ldg(&bg[c0 + j]);
            lo += bv; hi += bv;
            t[2 * p][j]     = (lo > 0.f) ? lo : NEG_SLOPE * lo;
            t[2 * p + 1][j] = (hi > 0.f) ? hi : NEG_SLOPE * hi;
        }
    __syncthreads();

    for (int i = tid; i < DD * DD / 4; i += 256)
        ((float4*)sW)[i] = ((const float4*)Wm)[i];
#pragma unroll
    for (int i = 0; i < 8; i++)
#pragma unroll
        for (int j = 0; j < 4; j++) sX[c0 + j][r0 + i] = t[i][j];
    __syncthreads();

#pragma unroll
    for (int p = 0; p < 4; p++)
#pragma unroll
        for (int j = 0; j < 4; j++) acc[p][j] = 0ull;

#pragma unroll 8
    for (int k = 0; k < DD; k++) {
        ulonglong2 A0 = *(const ulonglong2*)&sX[k][r0];
        ulonglong2 A1 = *(const ulonglong2*)&sX[k][r0 + 4];
        float4 bv = *(const float4*)&sW[k][c0];
        u64 B0 = pk2(bv.x, bv.x), B1 = pk2(bv.y, bv.y);
        u64 B2 = pk2(bv.z, bv.z), B3 = pk2(bv.w, bv.w);
        acc[0][0] = fma2(A0.x, B0, acc[0][0]); acc[0][1] = fma2(A0.x, B1, acc[0][1]);
        acc[0][2] = fma2(A0.x, B2, acc[0][2]); acc[0][3] = fma2(A0.x, B3, acc[0][3]);
        acc[1][0] = fma2(A0.y, B0, acc[1][0]); acc[1][1] = fma2(A0.y, B1, acc[1][1]);
        acc[1][2] = fma2(A0.y, B2, acc[1][2]); acc[1][3] = fma2(A0.y, B3, acc[1][3]);
        acc[2][0] = fma2(A1.x, B0, acc[2][0]); acc[2][1] = fma2(A1.x, B1, acc[2][1]);
        acc[2][2] = fma2(A1.x, B2, acc[2][2]); acc[2][3] = fma2(A1.x, B3, acc[2][3]);
        acc[3][0] = fma2(A1.y, B0, acc[3][0]); acc[3][1] = fma2(A1.y, B1, acc[3][1]);
        acc[3][2] = fma2(A1.y, B2, acc[3][2]); acc[3][3] = fma2(A1.y, B3, acc[3][3]);
    }

    float y[8][4];
#pragma unroll
    for (int p = 0; p < 4; p++)
#pragma unroll
        for (int j = 0; j < 4; j++) {
            float lo, hi;
            upk2(acc[p][j], lo, hi);
            float bv = __ldg(&bm[c0 + j]);
            y[2 * p][j] = lo + bv;
            y[2 * p + 1][j] = hi + bv;
        }

    float* nbuf = (layer == 0) ? g_n1 : g_n2;
#pragma unroll
    for (int i = 0; i < 8; i++) {
        float ss = y[i][0] * y[i][0] + y[i][1] * y[i][1] + y[i][2] * y[i][2] + y[i][3] * y[i][3];
#pragma unroll
        for (int o = 8; o > 0; o >>= 1) ss += __shfl_xor_sync(0xffffffffu, ss, o, 16);
        float inv = 1.f / fmaxf(sqrtf(ss), 1e-12f);
        int gr = rowBase + r0 + i;
        if (gr < NC) {
            if (layer == 0) {
                u32 lo = bf2(y[i][0], y[i][1]), hi = bf2(y[i][2], y[i][3]);
                *(u64*)&g_egoh[(size_t)gr * 32 + c0 / 2] = ((u64)hi << 32) | lo;
            }
            *(float4*)&nbuf[(size_t)gr * DD + c0] =
                make_float4(y[i][0] * inv, y[i][1] * inv, y[i][2] * inv, y[i][3] * inv);
        }
    }
}

// ---------------- BPR scoring + regularization ------------------------------------
__global__ void k_score(const int* __restrict__ user, const int* __restrict__ pos,
                        const int* __restrict__ neg, const float* __restrict__ uemb,
                        const float* __restrict__ iemb) {
    __shared__ float sb[8];
    __shared__ float sr[8];
    int tid = threadIdx.x;
    int wid = tid >> 5, lane = tid & 31;
    int b = blockIdx.x * 8 + wid;
    float sp = 0.f, rg = 0.f;
    if (b < BB) {
        int uu = user[b], pp = pos[b], nn = neg[b];
        size_t off = (size_t)lane * 2;
        const float* u0 = uemb + (size_t)uu * DD + off;
        const float* p0 = iemb + (size_t)pp * DD + off;
        const float* n0 = iemb + (size_t)nn * DD + off;
        const float* u1 = g_n1 + (size_t)uu * DD + off;
        const float* p1 = g_n1 + (size_t)(UC + pp) * DD + off;
        const float* n1 = g_n1 + (size_t)(UC + nn) * DD + off;
        const float* u2 = g_n2 + (size_t)uu * DD + off;
        const float* p2 = g_n2 + (size_t)(UC + pp) * DD + off;
        const float* n2 = g_n2 + (size_t)(UC + nn) * DD + off;
        float ps = 0.f, ns = 0.f;
        float2 ue = *(const float2*)u0, pe = *(const float2*)p0, ne = *(const float2*)n0;
        rg += ue.x * ue.x + ue.y * ue.y + pe.x * pe.x + pe.y * pe.y + ne.x * ne.x + ne.y * ne.y;
        ps += ue.x * pe.x + ue.y * pe.y;
        ns += ue.x * ne.x + ue.y * ne.y;
        float2 a1 = *(const float2*)u1, b1 = *(const float2*)p1, c1 = *(const float2*)n1;
        ps += a1.x * b1.x + a1.y * b1.y;
        ns += a1.x * c1.x + a1.y * c1.y;
        float2 a2 = *(const float2*)u2, b2 = *(const float2*)p2, c2 = *(const float2*)n2;
        ps += a2.x * b2.x + a2.y * b2.y;
        ns += a2.x * c2.x + a2.y * c2.y;
#pragma unroll
        for (int o = 16; o > 0; o >>= 1) {
            ps += __shfl_xor_sync(0xffffffffu, ps, o);
            ns += __shfl_xor_sync(0xffffffffu, ns, o);
            rg += __shfl_xor_sync(0xffffffffu, rg, o);
        }
        float x = ns - ps;
        sp = fmaxf(x, 0.f) + log1pf(expf(-fabsf(x)));
    }
    if (lane == 0) { sb[wid] = sp; sr[wid] = rg; }
    __syncthreads();
    if (tid == 0) {
        float s1 = 0.f, s2 = 0.f;
        for (int i = 0; i < 8; i++) { s1 += sb[i]; s2 += sr[i]; }
        atomicAdd(&g_acc[0], (double)s1);
        atomicAdd(&g_acc[1], (double)s2);
    }
}

__global__ void k_final(float* out) {
    out[0] = (float)(g_acc[0] / (double)BB);
    out[1] = (float)(0.0001 * 0.5 * g_acc[1] / (double)BB);
}

// ---------------- launch -----------------------------------------------------------
extern "C" void kernel_launch(void* const* d_in, const int* in_sizes, int n_in,
                              void* d_out, int out_size) {
    (void)in_sizes; (void)n_in; (void)out_size;
    const int*   user = (const int*)d_in[0];
    const int*   pos  = (const int*)d_in[1];
    const int*   neg  = (const int*)d_in[2];
    const int*   rows = (const int*)d_in[3];
    const int*   cols = (const int*)d_in[4];
    const float* vals = (const float*)d_in[5];
    const float* uemb = (const float*)d_in[6];
    const float* iemb = (const float*)d_in[7];
    const float* Wg0  = (const float*)d_in[8];
    const float* bg0  = (const float*)d_in[9];
    const float* Wm0  = (const float*)d_in[10];
    const float* bm0  = (const float*)d_in[11];
    const float* Wg1  = (const float*)d_in[12];
    const float* bg1  = (const float*)d_in[13];
    const float* Wm1  = (const float*)d_in[14];
    const float* bm1  = (const float*)d_in[15];
    float* out = (float*)d_out;

    u32* e0h  = nullptr;
    u32* egoh = nullptr;
    void* cntp = nullptr;
    void* accp = nullptr;
    cudaGetSymbolAddress((void**)&e0h, g_e0h);
    cudaGetSymbolAddress((void**)&egoh, g_egoh);
    cudaGetSymbolAddress(&cntp, g_cnt);
    cudaGetSymbolAddress(&accp, g_acc);

    cudaMemsetAsync(cntp, 0, NC * sizeof(int));
    cudaMemsetAsync(accp, 0, 2 * sizeof(double));

    k_inithist<<<2048, 256>>>(rows, uemb, iemb);
    k_scan1<<<NB, 256>>>();
    k_scan2<<<1, 1024>>>();
    k_scan3<<<NB, 256>>>();
    k_scatter<<<2048, 256>>>(rows, cols, vals);

    int spmm_blocks = (NC * 32 + 255) / 256;
    int gemm_blocks = (NC + 127) / 128;

    k_spmm<<<spmm_blocks, 256>>>(e0h);
    k_gemm<<<gemm_blocks, 256>>>(Wg0, bg0, Wm0, bm0, 0);
    k_spmm<<<spmm_blocks, 256>>>(egoh);
    k_gemm<<<gemm_blocks, 256>>>(Wg1, bg1, Wm1, bm1, 1);

    k_score<<<(BB + 7) / 8, 256>>>(user, pos, neg, uemb, iemb);
    k_final<<<1, 1>>>(out);
}